// round 14
// baseline (speedup 1.0000x reference)
#include <cuda_runtime.h>
#include <math.h>

#define INPUT 40
#define HID   512
#define LAT   128
#define BATCH 1024
#define SEQ   512

#define NTH   512
#define CLS   2                  // cluster size (CTAs per cluster)
#define ROWS  16                 // batch rows per cluster
#define RB    8                  // rows per thread (one row-group)
#define UPC   256                // big-cell units per CTA (HID / CLS)
#define NBLK  ((BATCH / ROWS) * CLS)   // 64 clusters * 2 = 128 CTAs

typedef unsigned long long u64;

// ---------------- device scratch ----------------
// big cells (h, d1): gate-interleaved quad layout Wq[k][j*4+g], g in {i,f,g,o}
__device__ __align__(16) float g_WqiT_h [INPUT * 4*HID];
__device__ __align__(16) float g_WqhT_h [HID   * 4*HID];
__device__ __align__(16) float g_b_h    [4*HID];
__device__ __align__(16) float g_WqiT_d1[LAT * 4*HID];
__device__ __align__(16) float g_WqhT_d1[HID * 4*HID];
__device__ __align__(16) float g_b_d1   [4*HID];
// small cells: plain transposed WT[k][G]
__device__ __align__(16) float g_WiT_mu[HID * 4*LAT];
__device__ __align__(16) float g_WhT_mu[LAT * 4*LAT];
__device__ __align__(16) float g_b_mu  [4*LAT];
__device__ __align__(16) float g_WiT_lv[HID * 4*LAT];
__device__ __align__(16) float g_WhT_lv[LAT * 4*LAT];
__device__ __align__(16) float g_b_lv  [4*LAT];
__device__ __align__(16) float g_WiT_d2[HID   * 4*INPUT];
__device__ __align__(16) float g_WhT_d2[INPUT * 4*INPUT];
__device__ __align__(16) float g_b_d2  [4*INPUT];

// ---------------- prep ----------------
__device__ __forceinline__ void transpose_dev(const float* __restrict__ W,
                                              float* __restrict__ WT,
                                              int G, int K, int tid, int nt)
{
    int n = G * K;
    for (int i = tid; i < n; i += nt) {
        int k = i / G;
        int g = i - k * G;
        WT[i] = W[g * K + k];
    }
}

// Wq[k*(4*HID) + j*4 + g] = W[(g*HID + j)*K + k]
__device__ __forceinline__ void make_quad(const float* __restrict__ W,
                                          float* __restrict__ Wq,
                                          int K, int tid, int nt)
{
    int n = K * 4 * HID;
    for (int i = tid; i < n; i += nt) {
        int k   = i / (4 * HID);
        int col = i - k * 4 * HID;
        int j   = col >> 2;
        int g   = col & 3;
        Wq[i] = W[(g * HID + j) * K + k];
    }
}

__global__ void prep_kernel(
    const float* Wih_h,  const float* Whh_h,  const float* bih_h,  const float* bhh_h,
    const float* Wih_mu, const float* Whh_mu, const float* bih_mu, const float* bhh_mu,
    const float* Wih_lv, const float* Whh_lv, const float* bih_lv, const float* bhh_lv,
    const float* Wih_d1, const float* Whh_d1, const float* bih_d1, const float* bhh_d1,
    const float* Wih_d2, const float* Whh_d2, const float* bih_d2, const float* bhh_d2)
{
    int tid = blockIdx.x * blockDim.x + threadIdx.x;
    int nt  = gridDim.x * blockDim.x;

    make_quad(Wih_h,  g_WqiT_h,  INPUT, tid, nt);
    make_quad(Whh_h,  g_WqhT_h,  HID,   tid, nt);
    make_quad(Wih_d1, g_WqiT_d1, LAT,   tid, nt);
    make_quad(Whh_d1, g_WqhT_d1, HID,   tid, nt);

    transpose_dev(Wih_mu, g_WiT_mu, 4*LAT, HID,   tid, nt);
    transpose_dev(Whh_mu, g_WhT_mu, 4*LAT, LAT,   tid, nt);
    transpose_dev(Wih_lv, g_WiT_lv, 4*LAT, HID,   tid, nt);
    transpose_dev(Whh_lv, g_WhT_lv, 4*LAT, LAT,   tid, nt);
    transpose_dev(Wih_d2, g_WiT_d2, 4*INPUT, HID,   tid, nt);
    transpose_dev(Whh_d2, g_WhT_d2, 4*INPUT, INPUT, tid, nt);

    for (int i = tid; i < 4*HID;   i += nt) g_b_h[i]  = bih_h[i]  + bhh_h[i];
    for (int i = tid; i < 4*LAT;   i += nt) g_b_mu[i] = bih_mu[i] + bhh_mu[i];
    for (int i = tid; i < 4*LAT;   i += nt) g_b_lv[i] = bih_lv[i] + bhh_lv[i];
    for (int i = tid; i < 4*HID;   i += nt) g_b_d1[i] = bih_d1[i] + bhh_d1[i];
    for (int i = tid; i < 4*INPUT; i += nt) g_b_d2[i] = bih_d2[i] + bhh_d2[i];
}

// ---------------- fast activations ----------------
__device__ __forceinline__ float tanh_fast(float x)
{
    float y;
    asm("tanh.approx.f32 %0, %1;" : "=f"(y) : "f"(x));
    return y;
}
__device__ __forceinline__ float sigf(float x)
{
    return fmaf(tanh_fast(0.5f * x), 0.5f, 0.5f);
}

// ---------------- packed f32x2 helpers ----------------
__device__ __forceinline__ void ffma2(u64& d, u64 a, u64 b)
{
    asm("fma.rn.f32x2 %0, %1, %2, %0;" : "+l"(d) : "l"(a), "l"(b));
}
__device__ __forceinline__ u64 pack2(float lo, float hi)
{
    u64 r;
    asm("mov.b64 %0, {%1, %2};" : "=l"(r) : "f"(lo), "f"(hi));
    return r;
}
__device__ __forceinline__ void unpack2(u64 v, float& lo, float& hi)
{
    asm("mov.b64 {%0, %1}, %2;" : "=f"(lo), "=f"(hi) : "l"(v));
}
__device__ __forceinline__ u64 add2(u64 a, u64 b)
{
    u64 d;
    asm("add.rn.f32x2 %0, %1, %2;" : "=l"(d) : "l"(a), "l"(b));
    return d;
}
__device__ __forceinline__ u64 shfl_xor1_u64(u64 v)
{
    unsigned lo = (unsigned)v, hi = (unsigned)(v >> 32);
    lo = __shfl_xor_sync(0xffffffffu, lo, 1);
    hi = __shfl_xor_sync(0xffffffffu, hi, 1);
    return ((u64)hi << 32) | lo;
}

// ---------------- cluster helpers ----------------
__device__ __forceinline__ void cluster_sync_()
{
    asm volatile("barrier.cluster.arrive.aligned;\n\t"
                 "barrier.cluster.wait.aligned;" ::: "memory");
}
__device__ __forceinline__ unsigned cluster_rank_()
{
    unsigned r;
    asm("mov.u32 %0, %%cluster_ctarank;" : "=r"(r));
    return r;
}
__device__ __forceinline__ unsigned smem_u32(const void* p)
{
    unsigned a;
    asm("{ .reg .u64 t; cvta.to.shared.u64 t, %1; cvt.u32.u64 %0, t; }"
        : "=r"(a) : "l"(p));
    return a;
}
__device__ __forceinline__ void st_peer_u64(unsigned local_addr, unsigned peer_rank, u64 v)
{
    asm volatile("{ .reg .b32 ra; mapa.shared::cluster.u32 ra, %0, %1; "
                 "st.shared::cluster.b64 [ra], %2; }"
                 :: "r"(local_addr), "r"(peer_rank), "l"(v) : "memory");
}

// ---------------- big-cell GEMM: quad gates per unit, 2k per iter ----------------
template<int K>
__device__ __forceinline__ void accum_quad(const u64* __restrict__ aDup,   // smem dup, rows stride K
                                           const float* __restrict__ Wq,   // gmem [K][4*HID]
                                           int j4, u64 (&accIF)[RB], u64 (&accGO)[RB])
{
    #pragma unroll 2
    for (int k = 0; k < K; k += 2) {
        ulonglong2 a2[RB];
        #pragma unroll
        for (int r = 0; r < RB; r++)
            a2[r] = *reinterpret_cast<const ulonglong2*>(aDup + r * K + k);

        ulonglong2 w0 = *reinterpret_cast<const ulonglong2*>(Wq + (size_t)k * (4*HID) + j4);
        ulonglong2 w1 = *reinterpret_cast<const ulonglong2*>(Wq + (size_t)(k+1) * (4*HID) + j4);

        #pragma unroll
        for (int r = 0; r < RB; r++) {
            ffma2(accIF[r], a2[r].x, w0.x);
            ffma2(accGO[r], a2[r].x, w0.y);
        }
        #pragma unroll
        for (int r = 0; r < RB; r++) {
            ffma2(accIF[r], a2[r].y, w1.x);
            ffma2(accGO[r], a2[r].y, w1.y);
        }
    }
}

// ---------------- small-cell GEMM: 4 gates (2 pairs) per thread, runtime k range ----------------
__device__ __forceinline__ void accum2_rt(const u64* __restrict__ aDup, int K,
                                          int k0, int k1,
                                          const float* __restrict__ WT, int G, int g0,
                                          u64 (&acc)[2][RB])
{
    #pragma unroll 2
    for (int k = k0; k < k1; k += 2) {
        ulonglong2 a2[RB];
        #pragma unroll
        for (int r = 0; r < RB; r++)
            a2[r] = *reinterpret_cast<const ulonglong2*>(aDup + r * K + k);

        ulonglong2 w0 = *reinterpret_cast<const ulonglong2*>(WT + (size_t)k * G + g0);
        ulonglong2 w1 = *reinterpret_cast<const ulonglong2*>(WT + (size_t)(k+1) * G + g0);

        #pragma unroll
        for (int r = 0; r < RB; r++) {
            ffma2(acc[0][r], a2[r].x, w0.x);
            ffma2(acc[1][r], a2[r].x, w0.y);
        }
        #pragma unroll
        for (int r = 0; r < RB; r++) {
            ffma2(acc[0][r], a2[r].y, w1.x);
            ffma2(acc[1][r], a2[r].y, w1.y);
        }
    }
}

// d2 helper (gate-pair, scalar k, runtime range)
template<int NGP>
__device__ __forceinline__ void accum_pairs_rt(const u64* __restrict__ aDup, int K,
                                               int k0, int k1,
                                               const float* __restrict__ WT,
                                               int G, int g0, u64 (&acc)[NGP][RB])
{
    #pragma unroll 4
    for (int k = k0; k < k1; k++) {
        u64 a[RB];
        #pragma unroll
        for (int r = 0; r < RB; r++) a[r] = aDup[r * K + k];
        const u64* w = reinterpret_cast<const u64*>(WT + (size_t)k * G + g0);
        u64 wv[NGP];
        #pragma unroll
        for (int i = 0; i < NGP; i++) wv[i] = w[i];
        #pragma unroll
        for (int i = 0; i < NGP; i++)
            #pragma unroll
            for (int r = 0; r < RB; r++)
                ffma2(acc[i][r], a[r], wv[i]);
    }
}

// ---------------- main persistent cluster kernel ----------------
extern __shared__ float smem[];

__global__ void __launch_bounds__(NTH, 1) vae_kernel(
    const float* __restrict__ x,     // [B][S][INPUT]
    const float* __restrict__ eps,   // [B][S][LAT]
    float* __restrict__ out)         // recon ++ mu ++ logvar
{
    // smem layout (floats); all "Dup" arrays are u64 (value,value) pairs
    float* gates  = smem;                          // 16*512      = 8192  (mu|lv gates / d2 partials)
    float* hDup   = gates + ROWS * 4 * LAT;        // 16*512*2    = 16384 (full h, 16 rows x 512 units)
    float* hsml   = hDup + ROWS * HID * 2;         // 16*128*2    = 4096  (hm on CTA0, hl on CTA1)
    float* csml   = hsml + ROWS * LAT * 2;         // 16*128      = 2048
    float* h2Dup  = csml + ROWS * LAT;             // 8*40*2      = 640   (local 8 rows)
    float* c2T    = h2Dup + RB * INPUT * 2;        // 8*40        = 320
    float* xzA    = c2T + RB * INPUT;              // 16*128*2    = 4096
    float* xzB    = xzA + ROWS * LAT * 2;          // 4096

    u64* hDupU  = reinterpret_cast<u64*>(hDup);
    u64* hsmlU  = reinterpret_cast<u64*>(hsml);
    u64* h2DupU = reinterpret_cast<u64*>(h2Dup);

    const int t    = threadIdx.x;
    const unsigned rank = cluster_rank_();
    const unsigned peer = rank ^ 1u;
    const int r0c  = (blockIdx.x >> 1) * ROWS;     // first batch row of this cluster

    float* reconO = out;
    float* muO    = out + (size_t)BATCH * SEQ * INPUT;
    float* lvO    = muO + (size_t)BATCH * SEQ * LAT;

    const unsigned hDupAddr = smem_u32(hDup);

    // big-cell mapping: unit-in-slice u, row group rg
    const int u   = t & (UPC - 1);       // 0..255
    const int rg  = t >> 8;              // 0/1 -> rows rg*8 .. rg*8+8
    const int j   = (int)rank * UPC + u; // global unit 0..511
    const int j4  = j * 4;

    // small-cell (mu/lv) mapping: lane-pair K-split + row half
    const int kchunk = t & 1;
    const int p      = (t >> 1) & 127;   // gate quad 0..127
    const int rh     = t >> 8;           // row half: rows rh*8 ..
    const int g0s    = p * 4;

    // d2 elementwise mapping (320 items over local 8 rows)
    const int exr = (t < INPUT * RB) ? t / INPUT : 0;
    const int exk = (t < INPUT * RB) ? t - exr * INPUT : 0;

    float cReg[RB];   // big-cell c state: unit j, rows rg*8..rg*8+8

    // ---- init encoder state (all local) ----
    #pragma unroll
    for (int r = 0; r < RB; r++) cReg[r] = 0.f;
    for (int i = t; i < ROWS * HID; i += NTH) hDupU[i] = 0ull;
    for (int i = t; i < ROWS * LAT; i += NTH) { hsmlU[i] = 0ull; csml[i] = 0.f; }
    // stage x_0: 16 rows x 40
    for (int idx = t; idx < ROWS * INPUT; idx += NTH) {
        int r = idx / INPUT, k2 = idx - r * INPUT;
        float v = x[((size_t)(r0c + r) * SEQ + 0) * INPUT + k2];
        reinterpret_cast<u64*>(xzA)[idx] = pack2(v, v);
    }
    __syncthreads();

    // ================= encoder =================
    for (int s = 0; s < SEQ; s++) {
        float* xzCur = (s & 1) ? xzB : xzA;
        float* xzNxt = (s & 1) ? xzA : xzB;

        // ---- P0: h-cell GEMM for unit j, rows rg*8.. ----
        float hNew[RB];
        {
            u64 accIF[RB], accGO[RB];
            u64 bIF = pack2(g_b_h[j], g_b_h[HID + j]);
            u64 bGO = pack2(g_b_h[2*HID + j], g_b_h[3*HID + j]);
            #pragma unroll
            for (int r = 0; r < RB; r++) { accIF[r] = bIF; accGO[r] = bGO; }

            accum_quad<INPUT>(reinterpret_cast<const u64*>(xzCur) + rg * RB * INPUT,
                              g_WqiT_h, j4, accIF, accGO);
            accum_quad<HID>(hDupU + rg * RB * HID, g_WqhT_h, j4, accIF, accGO);

            #pragma unroll
            for (int r = 0; r < RB; r++) {
                float xi, xf, xg, xo;
                unpack2(accIF[r], xi, xf);
                unpack2(accGO[r], xg, xo);
                float c = sigf(xf) * cReg[r] + sigf(xi) * tanh_fast(xg);
                float h = sigf(xo) * tanh_fast(c);
                cReg[r] = c;
                hNew[r] = h;
            }
        }
        cluster_sync_();   // everyone (both CTAs) done reading hDup old

        // ---- P1: publish h (local + peer DSMEM), stage x_{s+1} ----
        #pragma unroll
        for (int r = 0; r < RB; r++) {
            int row = rg * RB + r;
            u64 v = pack2(hNew[r], hNew[r]);
            hDupU[row * HID + j] = v;
            st_peer_u64(hDupAddr + (unsigned)(row * HID + j) * 8u, peer, v);
        }
        if (s + 1 < SEQ) {
            for (int idx = t; idx < ROWS * INPUT; idx += NTH) {
                int r = idx / INPUT, k2 = idx - r * INPUT;
                float v = x[((size_t)(r0c + r) * SEQ + (s + 1)) * INPUT + k2];
                reinterpret_cast<u64*>(xzNxt)[idx] = pack2(v, v);
            }
        }
        cluster_sync_();   // hDup new visible cluster-wide

        // ---- P2: mu (CTA0) / lv (CTA1) GEMM, 16 rows, lane-pair K-split ----
        {
            const float* Wi = rank ? g_WiT_lv : g_WiT_mu;
            const float* Wh = rank ? g_WhT_lv : g_WhT_mu;
            const float* bb = rank ? g_b_lv   : g_b_mu;

            u64 acc[2][RB];
            if (kchunk == 0) {
                u64 b0 = pack2(bb[g0s], bb[g0s + 1]);
                u64 b1 = pack2(bb[g0s + 2], bb[g0s + 3]);
                #pragma unroll
                for (int r = 0; r < RB; r++) { acc[0][r] = b0; acc[1][r] = b1; }
                accum2_rt(hDupU + rh * RB * HID, HID, 0, 320, Wi, 4*LAT, g0s, acc);
            } else {
                #pragma unroll
                for (int r = 0; r < RB; r++) { acc[0][r] = 0ull; acc[1][r] = 0ull; }
                accum2_rt(hDupU + rh * RB * HID, HID, 320, HID, Wi, 4*LAT, g0s, acc);
                accum2_rt(hsmlU + rh * RB * LAT, LAT, 0,   LAT, Wh, 4*LAT, g0s, acc);
            }
            #pragma unroll
            for (int i = 0; i < 2; i++)
                #pragma unroll
                for (int r = 0; r < RB; r++)
                    acc[i][r] = add2(acc[i][r], shfl_xor1_u64(acc[i][r]));

            if (kchunk == 0) {
                u64* gcell = reinterpret_cast<u64*>(gates);
                #pragma unroll
                for (int r = 0; r < RB; r++) {
                    int row = rh * RB + r;
                    gcell[row * (2 * LAT) + 2 * p]     = acc[0][r];
                    gcell[row * (2 * LAT) + 2 * p + 1] = acc[1][r];
                }
            }
        }
        __syncthreads();

        // ---- P3: mu/lv elementwise (16 rows x 128 units) ----
        {
            float* outPtr = rank ? lvO : muO;
            for (int idx = t; idx < ROWS * LAT; idx += NTH) {
                int r  = idx >> 7;
                int jj = idx & (LAT - 1);
                const float* gr = gates + r * (4 * LAT);
                float xi = gr[jj];
                float xf = gr[jj + LAT];
                float xg = gr[jj + 2 * LAT];
                float xo = gr[jj + 3 * LAT];
                float c = sigf(xf) * csml[idx] + sigf(xi) * tanh_fast(xg);
                float h = sigf(xo) * tanh_fast(c);
                csml[idx] = c;
                hsmlU[idx] = pack2(h, h);
                outPtr[((size_t)(r0c + r) * SEQ + s) * LAT + jj] = h;
            }
        }
        // no trailing sync needed: hazards covered by next-iter cluster syncs
    }

    // ---- transition: order encoder gmem outputs cluster-wide, reset state ----
    cluster_sync_();
    #pragma unroll
    for (int r = 0; r < RB; r++) cReg[r] = 0.f;
    for (int i = t; i < ROWS * HID; i += NTH) hDupU[i] = 0ull;
    for (int i = t; i < RB * INPUT; i += NTH) { h2DupU[i] = 0ull; c2T[i] = 0.f; }
    // stage z_0 (16 rows x 128)
    for (int idx = t; idx < ROWS * LAT; idx += NTH) {
        int r = idx >> 7, k2 = idx & (LAT - 1);
        size_t off = ((size_t)(r0c + r) * SEQ + 0) * LAT + k2;
        float m = __ldcg(&muO[off]);
        float l = __ldcg(&lvO[off]);
        float v = fmaf(eps[off], __expf(0.5f * l), m);
        reinterpret_cast<u64*>(xzA)[idx] = pack2(v, v);
    }
    __syncthreads();

    // ================= decoder =================
    for (int s = 0; s < SEQ; s++) {
        float* xzCur = (s & 1) ? xzB : xzA;
        float* xzNxt = (s & 1) ? xzA : xzB;

        // ---- P0: d1 GEMM ----
        float hNew[RB];
        {
            u64 accIF[RB], accGO[RB];
            u64 bIF = pack2(g_b_d1[j], g_b_d1[HID + j]);
            u64 bGO = pack2(g_b_d1[2*HID + j], g_b_d1[3*HID + j]);
            #pragma unroll
            for (int r = 0; r < RB; r++) { accIF[r] = bIF; accGO[r] = bGO; }

            accum_quad<LAT>(reinterpret_cast<const u64*>(xzCur) + rg * RB * LAT,
                            g_WqiT_d1, j4, accIF, accGO);
            accum_quad<HID>(hDupU + rg * RB * HID, g_WqhT_d1, j4, accIF, accGO);

            #pragma unroll
            for (int r = 0; r < RB; r++) {
                float xi, xf, xg, xo;
                unpack2(accIF[r], xi, xf);
                unpack2(accGO[r], xg, xo);
                float c = sigf(xf) * cReg[r] + sigf(xi) * tanh_fast(xg);
                float h = sigf(xo) * tanh_fast(c);
                cReg[r] = c;
                hNew[r] = h;
            }
        }
        cluster_sync_();

        // ---- P1: publish h1 (local + peer), stage z_{s+1} ----
        #pragma unroll
        for (int r = 0; r < RB; r++) {
            int row = rg * RB + r;
            u64 v = pack2(hNew[r], hNew[r]);
            hDupU[row * HID + j] = v;
            st_peer_u64(hDupAddr + (unsigned)(row * HID + j) * 8u, peer, v);
        }
        if (s + 1 < SEQ) {
            for (int idx = t; idx < ROWS * LAT; idx += NTH) {
                int r = idx >> 7, k2 = idx & (LAT - 1);
                size_t off = ((size_t)(r0c + r) * SEQ + (s + 1)) * LAT + k2;
                float m = __ldcg(&muO[off]);
                float l = __ldcg(&lvO[off]);
                float v = fmaf(eps[off], __expf(0.5f * l), m);
                reinterpret_cast<u64*>(xzNxt)[idx] = pack2(v, v);
            }
        }
        cluster_sync_();

        // ---- P2: d2 GEMM on this CTA's 8 rows (K-split two thread groups) ----
        {
            constexpr int G2 = 4 * INPUT;   // 160
            const u64* hRows = hDupU + (int)rank * RB * HID;
            float* gA = gates;              // partial A [8][160]
            float* gB = gates + RB * G2;    // partial B [8][160]
            if (t < 80) {
                const int g0 = t * 2;
                u64 acc[1][RB];
                u64 bb = pack2(g_b_d2[g0], g_b_d2[g0 + 1]);
                #pragma unroll
                for (int r = 0; r < RB; r++) acc[0][r] = bb;
                accum_pairs_rt<1>(hRows, HID, 0, 256, g_WiT_d2, G2, g0, acc);
                #pragma unroll
                for (int r = 0; r < RB; r++)
                    *reinterpret_cast<u64*>(&gA[r * G2 + g0]) = acc[0][r];
            } else if (t >= 256 && t < 336) {
                const int g0 = (t - 256) * 2;
                u64 acc[1][RB];
                #pragma unroll
                for (int r = 0; r < RB; r++) acc[0][r] = 0ull;
                accum_pairs_rt<1>(hRows,  HID,   256, HID,   g_WiT_d2, G2, g0, acc);
                accum_pairs_rt<1>(h2DupU, INPUT, 0,   INPUT, g_WhT_d2, G2, g0, acc);
                #pragma unroll
                for (int r = 0; r < RB; r++)
                    *reinterpret_cast<u64*>(&gB[r * G2 + g0]) = acc[0][r];
            }
        }
        __syncthreads();

        // ---- P3: d2 elementwise + recon out ----
        if (t < INPUT * RB) {
            constexpr int G2 = 4 * INPUT;
            const float* gA = gates + exr * G2;
            const float* gB = gates + RB * G2 + exr * G2;
            const int jj = exk;
            float xi = gA[jj]             + gB[jj];
            float xf = gA[jj + INPUT]     + gB[jj + INPUT];
            float xg = gA[jj + 2 * INPUT] + gB[jj + 2 * INPUT];
            float xo = gA[jj + 3 * INPUT] + gB[jj + 3 * INPUT];
            const int idx = exr * INPUT + jj;
            float c = sigf(xf) * c2T[idx] + sigf(xi) * tanh_fast(xg);
            float h = sigf(xo) * tanh_fast(c);
            c2T[idx] = c;
            h2DupU[idx] = pack2(h, h);
            reconO[((size_t)(r0c + (int)rank * RB + exr) * SEQ + s) * INPUT + jj] = h;
        }
        // no trailing sync: next-iter cluster syncs cover all hazards
    }
}

// ---------------- launcher ----------------
extern "C" void kernel_launch(void* const* d_in, const int* in_sizes, int n_in,
                              void* d_out, int out_size)
{
    (void)in_sizes; (void)n_in; (void)out_size;

    const float* x   = (const float*)d_in[0];
    const float* eps = (const float*)d_in[1];

    prep_kernel<<<512, 256>>>(
        (const float*)d_in[2],  (const float*)d_in[3],  (const float*)d_in[4],  (const float*)d_in[5],
        (const float*)d_in[6],  (const float*)d_in[7],  (const float*)d_in[8],  (const float*)d_in[9],
        (const float*)d_in[10], (const float*)d_in[11], (const float*)d_in[12], (const float*)d_in[13],
        (const float*)d_in[14], (const float*)d_in[15], (const float*)d_in[16], (const float*)d_in[17],
        (const float*)d_in[18], (const float*)d_in[19], (const float*)d_in[20], (const float*)d_in[21]);

    const int SMEM_FLOATS = ROWS*4*LAT            // gates               8192
                          + ROWS*HID*2            // hDup               16384
                          + ROWS*LAT*2            // hsml                4096
                          + ROWS*LAT              // csml                2048
                          + RB*INPUT*2            // h2Dup                640
                          + RB*INPUT              // c2T                  320
                          + 2 * ROWS*LAT*2;       // xzA, xzB            8192
    const int SMEM_BYTES = SMEM_FLOATS * (int)sizeof(float);   // 159488

    cudaFuncSetAttribute(vae_kernel, cudaFuncAttributeMaxDynamicSharedMemorySize, SMEM_BYTES);
    cudaFuncSetAttribute(vae_kernel, cudaFuncAttributeNonPortableClusterSizeAllowed, 1);

    cudaLaunchConfig_t cfg = {};
    cfg.gridDim  = dim3(NBLK, 1, 1);
    cfg.blockDim = dim3(NTH, 1, 1);
    cfg.dynamicSmemBytes = SMEM_BYTES;
    cudaLaunchAttribute attrs[1];
    attrs[0].id = cudaLaunchAttributeClusterDimension;
    attrs[0].val.clusterDim.x = CLS;
    attrs[0].val.clusterDim.y = 1;
    attrs[0].val.clusterDim.z = 1;
    cfg.attrs = attrs;
    cfg.numAttrs = 1;

    cudaLaunchKernelEx(&cfg, vae_kernel, x, eps, (float*)d_out);
}

// round 15
// speedup vs baseline: 6.4271x; 6.4271x over previous
#include <cuda_runtime.h>
#include <cuda_fp16.h>
#include <math.h>

#define INPUT 40
#define HID   512
#define LAT   128
#define BATCH 1024
#define SEQ   512
#define NTH   512
#define CLS   2
#define ROWS  16
#define NBLK  128

#define NKC_H  35   // 48(pad x) + 512
#define NKC_S  40   // 512 + 128
#define NKC_D1 40   // 128 + 512
#define NKC_D2 35   // 512 + 48(pad h2)

typedef unsigned long long u64;
typedef unsigned int u32;

// ---------------- device scratch: A-fragment fp16 weights ----------------
__device__ __align__(16) uint4 g_A_h [128 * NKC_H  * 32];
__device__ __align__(16) uint4 g_A_d1[128 * NKC_D1 * 32];
__device__ __align__(16) uint4 g_A_mu[ 32 * NKC_S  * 32];
__device__ __align__(16) uint4 g_A_lv[ 32 * NKC_S  * 32];
__device__ __align__(16) uint4 g_A_d2[ 10 * NKC_D2 * 32];
__device__ float g_b_h [4*HID];
__device__ float g_b_mu[4*LAT];
__device__ float g_b_lv[4*LAT];
__device__ float g_b_d1[4*HID];
__device__ float g_b_d2[4*INPUT];

// ---------------- prep: build fp16 A-fragments ----------------
__device__ __forceinline__ float wval(const float* Wih, const float* Whh,
                                      int Kinp, int Kpad, int Krec, int gate, int k)
{
    if (k < Kinp) return Wih[gate * Kinp + k];
    if (k >= Kpad && k < Kpad + Krec) return Whh[gate * Krec + (k - Kpad)];
    return 0.f;
}

__device__ __forceinline__ void fill_f16(const float* Wih, const float* Whh,
                                         int Kinp, int Kpad, int Krec, int NT, int NKC,
                                         u32* out, int tid, int nt)
{
    int n = NT * NKC * 128;
    for (int i = tid; i < n; i += nt) {
        int gt  = i / (NKC * 128);
        int rem = i - gt * (NKC * 128);
        int kc  = rem >> 7;
        int l   = rem & 127;
        int lane = l >> 2, reg = l & 3;
        int gate = gt * 16 + (lane >> 2) + ((reg & 1) ? 8 : 0);
        int k    = kc * 16 + (lane & 3) * 2 + ((reg & 2) ? 8 : 0);
        float v0 = wval(Wih, Whh, Kinp, Kpad, Krec, gate, k);
        float v1 = wval(Wih, Whh, Kinp, Kpad, Krec, gate, k + 1);
        __half2 hh = __floats2half2_rn(v0, v1);
        out[i] = *reinterpret_cast<u32*>(&hh);
    }
}

__global__ void prep_kernel(
    const float* Wih_h,  const float* Whh_h,  const float* bih_h,  const float* bhh_h,
    const float* Wih_mu, const float* Whh_mu, const float* bih_mu, const float* bhh_mu,
    const float* Wih_lv, const float* Whh_lv, const float* bih_lv, const float* bhh_lv,
    const float* Wih_d1, const float* Whh_d1, const float* bih_d1, const float* bhh_d1,
    const float* Wih_d2, const float* Whh_d2, const float* bih_d2, const float* bhh_d2)
{
    int tid = blockIdx.x * blockDim.x + threadIdx.x;
    int nt  = gridDim.x * blockDim.x;
    fill_f16(Wih_h,  Whh_h,  INPUT, 48,  HID,   128, NKC_H,  (u32*)g_A_h,  tid, nt);
    fill_f16(Wih_d1, Whh_d1, LAT,   LAT, HID,   128, NKC_D1, (u32*)g_A_d1, tid, nt);
    fill_f16(Wih_mu, Whh_mu, HID,   HID, LAT,    32, NKC_S,  (u32*)g_A_mu, tid, nt);
    fill_f16(Wih_lv, Whh_lv, HID,   HID, LAT,    32, NKC_S,  (u32*)g_A_lv, tid, nt);
    fill_f16(Wih_d2, Whh_d2, HID,   HID, INPUT,  10, NKC_D2, (u32*)g_A_d2, tid, nt);
    for (int i = tid; i < 4*HID;   i += nt) g_b_h[i]  = bih_h[i]  + bhh_h[i];
    for (int i = tid; i < 4*LAT;   i += nt) g_b_mu[i] = bih_mu[i] + bhh_mu[i];
    for (int i = tid; i < 4*LAT;   i += nt) g_b_lv[i] = bih_lv[i] + bhh_lv[i];
    for (int i = tid; i < 4*HID;   i += nt) g_b_d1[i] = bih_d1[i] + bhh_d1[i];
    for (int i = tid; i < 4*INPUT; i += nt) g_b_d2[i] = bih_d2[i] + bhh_d2[i];
}

// ---------------- helpers ----------------
__device__ __forceinline__ float tanh_fast(float x)
{ float y; asm("tanh.approx.f32 %0, %1;" : "=f"(y) : "f"(x)); return y; }
__device__ __forceinline__ float sigf(float x)
{ return fmaf(tanh_fast(0.5f * x), 0.5f, 0.5f); }
__device__ __forceinline__ u32 h2pack(float a, float b)
{ __half2 h = __floats2half2_rn(a, b); return *reinterpret_cast<u32*>(&h); }
__device__ __forceinline__ void cluster_sync_()
{ asm volatile("barrier.cluster.arrive.aligned;\n\tbarrier.cluster.wait.aligned;" ::: "memory"); }
__device__ __forceinline__ unsigned cluster_rank_()
{ unsigned r; asm("mov.u32 %0, %%cluster_ctarank;" : "=r"(r)); return r; }
__device__ __forceinline__ unsigned smem_u32a(const void* p)
{ unsigned a; asm("{ .reg .u64 t; cvta.to.shared.u64 t, %1; cvt.u32.u64 %0, t; }" : "=r"(a) : "l"(p)); return a; }
__device__ __forceinline__ void st_peer_u64(unsigned addr, unsigned peer, u64 v)
{
    asm volatile("{ .reg .b32 ra; mapa.shared::cluster.u32 ra, %0, %1; "
                 "st.shared::cluster.b64 [ra], %2; }" :: "r"(addr), "r"(peer), "l"(v) : "memory");
}
__device__ __forceinline__ void mma16(float (&d)[4], const uint4& a, u32 b0, u32 b1)
{
    asm volatile("mma.sync.aligned.m16n8k16.row.col.f32.f16.f16.f32 "
                 "{%0,%1,%2,%3},{%4,%5,%6,%7},{%8,%9},{%0,%1,%2,%3};"
                 : "+f"(d[0]), "+f"(d[1]), "+f"(d[2]), "+f"(d[3])
                 : "r"(a.x), "r"(a.y), "r"(a.z), "r"(a.w), "r"(b0), "r"(b1));
}

// ---------------- big-cell mma: 4 tiles/warp x 2 n-tiles ----------------
template<int NKC, int XKC>
__device__ __forceinline__ void big_mma(const uint4* __restrict__ A,
                                        const u32* __restrict__ xz, const u32* __restrict__ hT2,
                                        float* __restrict__ gB, int rank, int w, int lane)
{
    const int tg = lane & 3, gp = lane >> 2;
    float acc[4][2][4];
    #pragma unroll
    for (int c = 0; c < 4; c++)
        #pragma unroll
        for (int n = 0; n < 2; n++)
            #pragma unroll
            for (int q = 0; q < 4; q++) acc[c][n][q] = 0.f;

    for (int kc = 0; kc < NKC; kc++) {
        const u32* src; int k2;
        if (kc < XKC) { src = xz;  k2 = kc * 8 + tg; }
        else          { src = hT2; k2 = (kc - XKC) * 8 + tg; }
        u32 b00 = src[k2 * 16 + gp];
        u32 b01 = src[(k2 + 4) * 16 + gp];
        u32 b10 = src[k2 * 16 + 8 + gp];
        u32 b11 = src[(k2 + 4) * 16 + 8 + gp];
        #pragma unroll
        for (int c = 0; c < 4; c++) {
            uint4 a = A[((c * 32 + rank * 16 + w) * NKC + kc) * 32 + lane];
            mma16(acc[c][0], a, b00, b01);
            mma16(acc[c][1], a, b10, b11);
        }
    }
    #pragma unroll
    for (int c = 0; c < 4; c++) {
        int lg = c * 256 + w * 16 + gp;
        #pragma unroll
        for (int n = 0; n < 2; n++) {
            *(float2*)&gB[lg * 16 + n * 8 + 2 * tg]       = make_float2(acc[c][n][0], acc[c][n][1]);
            *(float2*)&gB[(lg + 8) * 16 + n * 8 + 2 * tg] = make_float2(acc[c][n][2], acc[c][n][3]);
        }
    }
}

// ---------------- big-cell elementwise (h in regs, shfl-paired half2) ----------------
__device__ __forceinline__ void big_elem(const float* __restrict__ gB, const float (&b4)[4],
                                         float (&cR)[8], int uB, int rg, u32 (&hp)[8])
{
    float G[4][8];
    #pragma unroll
    for (int g = 0; g < 4; g++) {
        const float* p = &gB[(g * 256 + uB) * 16 + rg * 8];
        float4 v0 = *(const float4*)p, v1 = *(const float4*)(p + 4);
        G[g][0]=v0.x; G[g][1]=v0.y; G[g][2]=v0.z; G[g][3]=v0.w;
        G[g][4]=v1.x; G[g][5]=v1.y; G[g][6]=v1.z; G[g][7]=v1.w;
    }
    #pragma unroll
    for (int r = 0; r < 8; r++) {
        float cv = sigf(G[1][r] + b4[1]) * cR[r] + sigf(G[0][r] + b4[0]) * tanh_fast(G[2][r] + b4[2]);
        float h  = sigf(G[3][r] + b4[3]) * tanh_fast(cv);
        cR[r] = cv;
        float other = __shfl_xor_sync(0xffffffffu, h, 2);
        hp[r] = h2pack(h, other);       // valid pair only on even-uB threads
    }
}

// ---------------- main persistent cluster kernel ----------------
extern __shared__ float smem[];

__global__ void __launch_bounds__(NTH, 1) vae_kernel(
    const float* __restrict__ x, const float* __restrict__ eps, float* __restrict__ out)
{
    float* gatesBig = smem;                        // 16384
    float* gatesSml = gatesBig + 16384;            //  8192
    float* d2g      = gatesSml + 8192;             //  1280
    u32*  hT2  = (u32*)(d2g + 1280);               //  4096  [256 k2][16]
    u32*  hs2  = hT2 + 4096;                       //  1024  [64 k2][16]
    u32*  h2T2 = hs2 + 1024;                       //   192  [24 k2][8]
    u32*  xzA  = h2T2 + 192;                       //  1024
    u32*  xzB  = xzA + 1024;                       //  1024
    float* csml = (float*)(xzB + 1024);            //  2048
    float* c2T  = csml + 2048;                     //   320

    const int t = threadIdx.x, w = t >> 5, lane = t & 31;
    const unsigned rank = cluster_rank_(), peer = rank ^ 1u;
    const int r0c = (blockIdx.x >> 1) * ROWS;

    float* reconO = out;
    float* muO    = out + (size_t)BATCH * SEQ * INPUT;
    float* lvO    = muO + (size_t)BATCH * SEQ * LAT;
    const unsigned hT2addr = smem_u32a(hT2);

    // mappings
    const int uB = t >> 1, rg = t & 1, jB = (int)rank * 256 + uB;   // big elementwise
    const int uS = t >> 2, rq = t & 3;                              // small elementwise
    // bias preloads
    float bh[4], bd1[4], bs[4], bd2[4];
    #pragma unroll
    for (int c = 0; c < 4; c++) { bh[c] = g_b_h[c*HID + jB]; bd1[c] = g_b_d1[c*HID + jB]; }
    const float* bsp = rank ? g_b_lv : g_b_mu;
    #pragma unroll
    for (int c = 0; c < 4; c++) bs[c] = bsp[c*LAT + uS];
    #pragma unroll
    for (int c = 0; c < 4; c++) bd2[c] = (t < 320) ? g_b_d2[c*INPUT + (t >> 3)] : 0.f;

    float cReg[8];

    // ---- encoder init ----
    #pragma unroll
    for (int r = 0; r < 8; r++) cReg[r] = 0.f;
    for (int i = t; i < 4096; i += NTH) hT2[i] = 0u;
    for (int i = t; i < 1024; i += NTH) hs2[i] = 0u;
    for (int i = t; i < 2048; i += NTH) csml[i] = 0.f;
    for (int idx = t; idx < 24 * 16; idx += NTH) {      // stage x_0 (zero-padded to k=48)
        int k2 = idx >> 4, row = idx & 15, k = 2 * k2;
        float v0 = (k < INPUT)     ? x[((size_t)(r0c + row) * SEQ) * INPUT + k]     : 0.f;
        float v1 = (k + 1 < INPUT) ? x[((size_t)(r0c + row) * SEQ) * INPUT + k + 1] : 0.f;
        xzA[idx] = h2pack(v0, v1);
    }
    __syncthreads();

    // ================= encoder =================
    for (int s = 0; s < SEQ; s++) {
        u32* xzC = (s & 1) ? xzB : xzA;
        u32* xzN = (s & 1) ? xzA : xzB;

        big_mma<NKC_H, 3>(g_A_h, xzC, hT2, gatesBig, (int)rank, w, lane);
        __syncthreads();

        u32 hp[8];
        big_elem(gatesBig, bh, cReg, uB, rg, hp);
        cluster_sync_();                    // both CTAs done reading hT2 old

        if ((uB & 1) == 0) {
            int base = (jB >> 1) * 16 + rg * 8;
            #pragma unroll
            for (int r = 0; r < 8; r++) hT2[base + r] = hp[r];
            #pragma unroll
            for (int r = 0; r < 8; r += 2)
                st_peer_u64(hT2addr + (unsigned)(base + r) * 4u, peer,
                            (u64)hp[r] | ((u64)hp[r+1] << 32));
        }
        if (s + 1 < SEQ) {
            for (int idx = t; idx < 24 * 16; idx += NTH) {
                int k2 = idx >> 4, row = idx & 15, k = 2 * k2;
                float v0 = (k < INPUT)     ? x[((size_t)(r0c + row) * SEQ + s + 1) * INPUT + k]     : 0.f;
                float v1 = (k + 1 < INPUT) ? x[((size_t)(r0c + row) * SEQ + s + 1) * INPUT + k + 1] : 0.f;
                xzN[idx] = h2pack(v0, v1);
            }
        }
        cluster_sync_();                    // hT2 new visible cluster-wide

        // small cell mma: mu (CTA0) / lv (CTA1), 2 tiles per warp
        {
            const uint4* A = rank ? g_A_lv : g_A_mu;
            const int tg = lane & 3, gp = lane >> 2;
            float acc[2][2][4];
            #pragma unroll
            for (int i = 0; i < 2; i++)
                #pragma unroll
                for (int n = 0; n < 2; n++)
                    #pragma unroll
                    for (int q = 0; q < 4; q++) acc[i][n][q] = 0.f;
            for (int kc = 0; kc < NKC_S; kc++) {
                const u32* src; int k2;
                if (kc < 32) { src = hT2; k2 = kc * 8 + tg; }
                else         { src = hs2; k2 = (kc - 32) * 8 + tg; }
                u32 b00 = src[k2 * 16 + gp];
                u32 b01 = src[(k2 + 4) * 16 + gp];
                u32 b10 = src[k2 * 16 + 8 + gp];
                u32 b11 = src[(k2 + 4) * 16 + 8 + gp];
                #pragma unroll
                for (int i = 0; i < 2; i++) {
                    uint4 a = A[((2 * w + i) * NKC_S + kc) * 32 + lane];
                    mma16(acc[i][0], a, b00, b01);
                    mma16(acc[i][1], a, b10, b11);
                }
            }
            #pragma unroll
            for (int i = 0; i < 2; i++) {
                int lg = (2 * w + i) * 16 + gp;
                #pragma unroll
                for (int n = 0; n < 2; n++) {
                    *(float2*)&gatesSml[lg * 16 + n * 8 + 2 * tg]       = make_float2(acc[i][n][0], acc[i][n][1]);
                    *(float2*)&gatesSml[(lg + 8) * 16 + n * 8 + 2 * tg] = make_float2(acc[i][n][2], acc[i][n][3]);
                }
            }
        }
        __syncthreads();

        // small elementwise: 4 rows per thread
        {
            float* outPtr = rank ? lvO : muO;
            float G[4][4];
            #pragma unroll
            for (int g = 0; g < 4; g++) {
                float4 v = *(const float4*)&gatesSml[(g * 128 + uS) * 16 + rq * 4];
                G[g][0]=v.x; G[g][1]=v.y; G[g][2]=v.z; G[g][3]=v.w;
            }
            #pragma unroll
            for (int rr = 0; rr < 4; rr++) {
                int row = rq * 4 + rr;
                int ci = uS * 16 + row;
                float cv = sigf(G[1][rr] + bs[1]) * csml[ci] + sigf(G[0][rr] + bs[0]) * tanh_fast(G[2][rr] + bs[2]);
                float h  = sigf(G[3][rr] + bs[3]) * tanh_fast(cv);
                csml[ci] = cv;
                float other = __shfl_xor_sync(0xffffffffu, h, 4);
                if ((uS & 1) == 0) hs2[(uS >> 1) * 16 + row] = h2pack(h, other);
                outPtr[((size_t)(r0c + row) * SEQ + s) * LAT + uS] = h;
            }
        }
    }

    // ---- transition ----
    cluster_sync_();
    #pragma unroll
    for (int r = 0; r < 8; r++) cReg[r] = 0.f;
    for (int i = t; i < 4096; i += NTH) hT2[i] = 0u;
    for (int i = t; i < 192;  i += NTH) h2T2[i] = 0u;
    for (int i = t; i < 320;  i += NTH) c2T[i] = 0.f;
    for (int idx = t; idx < 64 * 16; idx += NTH) {      // stage z_0
        int k2 = idx >> 4, row = idx & 15;
        size_t off = ((size_t)(r0c + row) * SEQ) * LAT + 2 * k2;
        float z0 = fmaf(eps[off],     __expf(0.5f * __ldcg(&lvO[off])),     __ldcg(&muO[off]));
        float z1 = fmaf(eps[off + 1], __expf(0.5f * __ldcg(&lvO[off + 1])), __ldcg(&muO[off + 1]));
        xzA[idx] = h2pack(z0, z1);
    }
    __syncthreads();

    // ================= decoder =================
    for (int s = 0; s < SEQ; s++) {
        u32* xzC = (s & 1) ? xzB : xzA;
        u32* xzN = (s & 1) ? xzA : xzB;

        big_mma<NKC_D1, 8>(g_A_d1, xzC, hT2, gatesBig, (int)rank, w, lane);
        __syncthreads();

        u32 hp[8];
        big_elem(gatesBig, bd1, cReg, uB, rg, hp);
        cluster_sync_();

        if ((uB & 1) == 0) {
            int base = (jB >> 1) * 16 + rg * 8;
            #pragma unroll
            for (int r = 0; r < 8; r++) hT2[base + r] = hp[r];
            #pragma unroll
            for (int r = 0; r < 8; r += 2)
                st_peer_u64(hT2addr + (unsigned)(base + r) * 4u, peer,
                            (u64)hp[r] | ((u64)hp[r+1] << 32));
        }
        if (s + 1 < SEQ) {
            for (int idx = t; idx < 64 * 16; idx += NTH) {
                int k2 = idx >> 4, row = idx & 15;
                size_t off = ((size_t)(r0c + row) * SEQ + s + 1) * LAT + 2 * k2;
                float z0 = fmaf(eps[off],     __expf(0.5f * __ldcg(&lvO[off])),     __ldcg(&muO[off]));
                float z1 = fmaf(eps[off + 1], __expf(0.5f * __ldcg(&lvO[off + 1])), __ldcg(&muO[off + 1]));
                xzN[idx] = h2pack(z0, z1);
            }
        }
        cluster_sync_();

        // d2 mma: warps 0..9, 1 tile each, this CTA's 8 rows
        if (w < 10) {
            const int tg = lane & 3, gp = lane >> 2;
            float acc[4] = {0.f, 0.f, 0.f, 0.f};
            for (int kc = 0; kc < NKC_D2; kc++) {
                u32 b0, b1;
                if (kc < 32) {
                    int k2 = kc * 8 + tg;
                    b0 = hT2[k2 * 16 + (int)rank * 8 + gp];
                    b1 = hT2[(k2 + 4) * 16 + (int)rank * 8 + gp];
                } else {
                    int k2 = (kc - 32) * 8 + tg;
                    b0 = h2T2[k2 * 8 + gp];
                    b1 = h2T2[(k2 + 4) * 8 + gp];
                }
                uint4 a = g_A_d2[(w * NKC_D2 + kc) * 32 + lane];
                mma16(acc, a, b0, b1);
            }
            *(float2*)&d2g[(w * 16 + gp) * 8 + 2 * tg]     = make_float2(acc[0], acc[1]);
            *(float2*)&d2g[(w * 16 + gp + 8) * 8 + 2 * tg] = make_float2(acc[2], acc[3]);
        }
        __syncthreads();

        // d2 elementwise: 320 unit-rows
        if (t < 320) {
            int u2 = t >> 3, row = t & 7;
            float G[4];
            #pragma unroll
            for (int g = 0; g < 4; g++) G[g] = d2g[(g * 40 + u2) * 8 + row];
            int ci = u2 * 8 + row;
            float cv = sigf(G[1] + bd2[1]) * c2T[ci] + sigf(G[0] + bd2[0]) * tanh_fast(G[2] + bd2[2]);
            float h  = sigf(G[3] + bd2[3]) * tanh_fast(cv);
            c2T[ci] = cv;
            float other = __shfl_xor_sync(0xffffffffu, h, 8);
            if ((u2 & 1) == 0) h2T2[(u2 >> 1) * 8 + row] = h2pack(h, other);
            reconO[((size_t)(r0c + (int)rank * 8 + row) * SEQ + s) * INPUT + u2] = h;
        }
    }
}

// ---------------- launcher ----------------
extern "C" void kernel_launch(void* const* d_in, const int* in_sizes, int n_in,
                              void* d_out, int out_size)
{
    (void)in_sizes; (void)n_in; (void)out_size;
    const float* x   = (const float*)d_in[0];
    const float* eps = (const float*)d_in[1];

    prep_kernel<<<512, 256>>>(
        (const float*)d_in[2],  (const float*)d_in[3],  (const float*)d_in[4],  (const float*)d_in[5],
        (const float*)d_in[6],  (const float*)d_in[7],  (const float*)d_in[8],  (const float*)d_in[9],
        (const float*)d_in[10], (const float*)d_in[11], (const float*)d_in[12], (const float*)d_in[13],
        (const float*)d_in[14], (const float*)d_in[15], (const float*)d_in[16], (const float*)d_in[17],
        (const float*)d_in[18], (const float*)d_in[19], (const float*)d_in[20], (const float*)d_in[21]);

    const int SMEM_BYTES = (16384 + 8192 + 1280 + 4096 + 1024 + 192 + 1024 + 1024 + 2048 + 320) * 4;
    cudaFuncSetAttribute(vae_kernel, cudaFuncAttributeMaxDynamicSharedMemorySize, SMEM_BYTES);
    cudaFuncSetAttribute(vae_kernel, cudaFuncAttributeNonPortableClusterSizeAllowed, 1);

    cudaLaunchConfig_t cfg = {};
    cfg.gridDim  = dim3(NBLK, 1, 1);
    cfg.blockDim = dim3(NTH, 1, 1);
    cfg.dynamicSmemBytes = SMEM_BYTES;
    cudaLaunchAttribute attrs[1];
    attrs[0].id = cudaLaunchAttributeClusterDimension;
    attrs[0].val.clusterDim.x = CLS;
    attrs[0].val.clusterDim.y = 1;
    attrs[0].val.clusterDim.z = 1;
    cfg.attrs = attrs;
    cfg.numAttrs = 1;
    cudaLaunchKernelEx(&cfg, vae_kernel, x, eps, (float*)d_out);
}